// round 2
// baseline (speedup 1.0000x reference)
#include <cuda_runtime.h>
#include <cstdint>

#define N_PTS 1000000
#define KNN   9
#define C     20
#define CIN3  23
#define TPB   256
#define NBLK  ((N_PTS + TPB - 1) / TPB)   // 3907
#define EPSV  1e-5f

// ---------------- scratch (device globals; allocation-free per contract) ----
__device__ __align__(16) float g_G0[N_PTS * C];   // W1f*feat + W1p*pts  (per point)
__device__ __align__(16) float g_P0[N_PTS * C];   // W1p*pts             (per point)
__device__ __align__(16) float g_v [N_PTS * C];   // first weighted aggregation
__device__ __align__(16) float g_x2[N_PTS * C];   // second weighted aggregation
__device__ __align__(16) float g_h [N_PTS * C];   // pre-BN3 linear output
__device__ float g_wgt[N_PTS * KNN];              // attention weights w[n,k]
__device__ float g_part[NBLK * 40];               // per-block partial sums (sum|sumsq)
__device__ float g_red[40];                       // reduced sums
__device__ float g_scale[C];                      // folded BN scale (reused per stage)
__device__ float g_bias[C];                       // folded BN bias  (reused per stage)
__device__ int   g_idx64;                         // 1 if index buffer is int64

// ---------------- helpers ---------------------------------------------------
__device__ __forceinline__ void load20(float* r, const float* p) {
    const float4* q = (const float4*)p;
#pragma unroll
    for (int i = 0; i < 5; i++) {
        float4 t = q[i];
        r[4*i] = t.x; r[4*i+1] = t.y; r[4*i+2] = t.z; r[4*i+3] = t.w;
    }
}
__device__ __forceinline__ void store20(float* p, const float* r) {
    float4* q = (float4*)p;
#pragma unroll
    for (int i = 0; i < 5; i++) {
        float4 t;
        t.x = r[4*i]; t.y = r[4*i+1]; t.z = r[4*i+2]; t.w = r[4*i+3];
        q[i] = t;
    }
}
__device__ __forceinline__ int fetch_idx(const void* p, int i, int is64) {
    return is64 ? (int)((const long long*)p)[i] : ((const int*)p)[i];
}

// deterministic per-block reduction of 20 sums + 20 sumsqs -> g_part[blk][0..39]
__device__ __forceinline__ void stats_reduce_store(float* s, float* q, int blk) {
#pragma unroll
    for (int o = 0; o < C; o++) {
#pragma unroll
        for (int off = 16; off > 0; off >>= 1) {
            s[o] += __shfl_down_sync(0xffffffffu, s[o], off);
            q[o] += __shfl_down_sync(0xffffffffu, q[o], off);
        }
    }
    __shared__ float sh[8][40];
    int warp = threadIdx.x >> 5, lane = threadIdx.x & 31;
    if (lane == 0) {
#pragma unroll
        for (int o = 0; o < C; o++) { sh[warp][o] = s[o]; sh[warp][20 + o] = q[o]; }
    }
    __syncthreads();
    if (threadIdx.x < 40) {
        float a = 0.f;
#pragma unroll
        for (int w = 0; w < 8; w++) a += sh[w][threadIdx.x];
        g_part[blk * 40 + threadIdx.x] = a;
    }
}

// ---------------- kernels ---------------------------------------------------

// detect index dtype: int64 values < 2^31 have all-zero high words
__global__ void k_detect(const void* idx) {
    if (threadIdx.x == 0) {
        const int* p = (const int*)idx;
        int odd_zero = 1;
        for (int i = 0; i < 64; i++)
            if (p[2 * i + 1] != 0) odd_zero = 0;
        g_idx64 = odd_zero;
    }
}

// per-point precompute: G0 = W1[:, :20]*feat + W1[:,20:]*pts ; P0 = W1[:,20:]*pts
__global__ void __launch_bounds__(TPB) k_prep(const float* __restrict__ pts,
                                              const float* __restrict__ feat,
                                              const float* __restrict__ W1) {
    __shared__ float sW[C * CIN3];
    for (int i = threadIdx.x; i < C * CIN3; i += TPB) sW[i] = W1[i];
    __syncthreads();
    int n = blockIdx.x * TPB + threadIdx.x;
    if (n >= N_PTS) return;
    float f[C];
    load20(f, &feat[n * C]);
    float p0 = pts[n*3], p1 = pts[n*3+1], p2 = pts[n*3+2];
    float G[C], P[C];
#pragma unroll
    for (int o = 0; o < C; o++) {
        const float* w = &sW[o * CIN3];
        float acc = 0.f;
#pragma unroll
        for (int c = 0; c < C; c++) acc = fmaf(w[c], f[c], acc);
        float pp = fmaf(w[22], p2, fmaf(w[21], p1, w[20] * p0));
        P[o] = pp;
        G[o] = acc + pp;
    }
    store20(&g_P0[n * C], P);
    store20(&g_G0[n * C], G);
}

// BN1 statistics: sum / sumsq over all 9M of (G0[idx] - P0[n]) per channel
__global__ void __launch_bounds__(TPB) k_stats1(const void* __restrict__ idxp) {
    int n = blockIdx.x * TPB + threadIdx.x;
    float s[C], q[C];
#pragma unroll
    for (int o = 0; o < C; o++) { s[o] = 0.f; q[o] = 0.f; }
    if (n < N_PTS) {
        int is64 = g_idx64;
        float P[C];
        load20(P, &g_P0[n * C]);
        int ib = n * KNN;
        for (int k = 0; k < KNN; k++) {
            int j = fetch_idx(idxp, ib + k, is64);
            const float4* gp = (const float4*)&g_G0[j * C];
#pragma unroll
            for (int i = 0; i < 5; i++) {
                float4 t = gp[i];
                float d0 = t.x - P[4*i],   d1 = t.y - P[4*i+1];
                float d2 = t.z - P[4*i+2], d3 = t.w - P[4*i+3];
                s[4*i]   += d0; q[4*i]   = fmaf(d0, d0, q[4*i]);
                s[4*i+1] += d1; q[4*i+1] = fmaf(d1, d1, q[4*i+1]);
                s[4*i+2] += d2; q[4*i+2] = fmaf(d2, d2, q[4*i+2]);
                s[4*i+3] += d3; q[4*i+3] = fmaf(d3, d3, q[4*i+3]);
            }
        }
    }
    stats_reduce_store(s, q, blockIdx.x);
}

// reduce g_part[NBLK][40] -> g_red[40]; grid = 40 blocks
__global__ void __launch_bounds__(256) k_reduce() {
    int slot = blockIdx.x;
    float acc = 0.f;
    for (int b = threadIdx.x; b < NBLK; b += 256) acc += g_part[b * 40 + slot];
    __shared__ float sh[256];
    sh[threadIdx.x] = acc;
    __syncthreads();
    for (int s = 128; s > 0; s >>= 1) {
        if (threadIdx.x < s) sh[threadIdx.x] += sh[threadIdx.x + s];
        __syncthreads();
    }
    if (threadIdx.x == 0) g_red[slot] = sh[0];
}

// fold BN -> scale/bias
__global__ void k_final(const float* __restrict__ g, const float* __restrict__ b,
                        float inv_count) {
    int o = threadIdx.x;
    if (o < C) {
        float mean = g_red[o] * inv_count;
        float var  = fmaf(-mean, mean, g_red[20 + o] * inv_count);
        float x = var + EPSV;
        float r = rsqrtf(x);
        r = r * (1.5f - 0.5f * x * r * r);   // Newton refine
        float sc = g[o] * r;
        g_scale[o] = sc;
        g_bias[o]  = b[o] - mean * sc;
    }
}

// first aggregation: x_k = s*G0[idx]+(t-s*P0[n]); w_k = x_k . x_0; v = sum_k x_k*w_k
__global__ void __launch_bounds__(TPB) k_agg1(const void* __restrict__ idxp) {
    __shared__ float ssc[C], sbi[C];
    if (threadIdx.x < C) { ssc[threadIdx.x] = g_scale[threadIdx.x]; sbi[threadIdx.x] = g_bias[threadIdx.x]; }
    __syncthreads();
    int n = blockIdx.x * TPB + threadIdx.x;
    if (n >= N_PTS) return;
    int is64 = g_idx64;
    float base[C];
    {
        float P[C];
        load20(P, &g_P0[n * C]);
#pragma unroll
        for (int o = 0; o < C; o++) base[o] = fmaf(-ssc[o], P[o], sbi[o]);
    }
    int ib = n * KNN;
    int j0 = fetch_idx(idxp, ib, is64);
    float x0[C];
    load20(x0, &g_G0[j0 * C]);
    float w0 = 0.f;
#pragma unroll
    for (int o = 0; o < C; o++) { x0[o] = fmaf(ssc[o], x0[o], base[o]); }
#pragma unroll
    for (int o = 0; o < C; o++) w0 = fmaf(x0[o], x0[o], w0);
    float v[C];
#pragma unroll
    for (int o = 0; o < C; o++) v[o] = x0[o] * w0;
    g_wgt[ib] = w0;
    for (int k = 1; k < KNN; k++) {
        int j = fetch_idx(idxp, ib + k, is64);
        float xk[C];
        load20(xk, &g_G0[j * C]);
        float wk = 0.f;
#pragma unroll
        for (int o = 0; o < C; o++) { xk[o] = fmaf(ssc[o], xk[o], base[o]); }
#pragma unroll
        for (int o = 0; o < C; o++) wk = fmaf(xk[o], x0[o], wk);
#pragma unroll
        for (int o = 0; o < C; o++) v[o] = fmaf(xk[o], wk, v[o]);
        g_wgt[ib + k] = wk;
    }
    store20(&g_v[n * C], v);
}

// second aggregation: x2[n] = sum_k v[idx[n,k]] * w[n,k]; plus BN2 stats
__global__ void __launch_bounds__(TPB) k_agg2(const void* __restrict__ idxp) {
    int n = blockIdx.x * TPB + threadIdx.x;
    float s[C], q[C];
#pragma unroll
    for (int o = 0; o < C; o++) { s[o] = 0.f; q[o] = 0.f; }
    if (n < N_PTS) {
        int is64 = g_idx64;
        int ib = n * KNN;
        float acc[C];
#pragma unroll
        for (int o = 0; o < C; o++) acc[o] = 0.f;
        for (int k = 0; k < KNN; k++) {
            float wk = g_wgt[ib + k];
            int j = fetch_idx(idxp, ib + k, is64);
            const float4* gp = (const float4*)&g_v[j * C];
#pragma unroll
            for (int i = 0; i < 5; i++) {
                float4 t = gp[i];
                acc[4*i]   = fmaf(t.x, wk, acc[4*i]);
                acc[4*i+1] = fmaf(t.y, wk, acc[4*i+1]);
                acc[4*i+2] = fmaf(t.z, wk, acc[4*i+2]);
                acc[4*i+3] = fmaf(t.w, wk, acc[4*i+3]);
            }
        }
        store20(&g_x2[n * C], acc);
#pragma unroll
        for (int o = 0; o < C; o++) { s[o] = acc[o]; q[o] = acc[o] * acc[o]; }
    }
    stats_reduce_store(s, q, blockIdx.x);
}

// refine stage 1: r = relu(bn2(x2)); h = Wr1 @ [r, feat] + br1; plus BN3 stats
__global__ void __launch_bounds__(TPB) k_refine1(const float* __restrict__ feat,
                                                 const float* __restrict__ Wr1,
                                                 const float* __restrict__ br1) {
    __shared__ float sW[C * 40], sb[C], ssc[C], sbi[C];
    for (int i = threadIdx.x; i < C * 40; i += TPB) sW[i] = Wr1[i];
    if (threadIdx.x < C) {
        sb[threadIdx.x]  = br1[threadIdx.x];
        ssc[threadIdx.x] = g_scale[threadIdx.x];
        sbi[threadIdx.x] = g_bias[threadIdx.x];
    }
    __syncthreads();
    int n = blockIdx.x * TPB + threadIdx.x;
    float s[C], q[C];
#pragma unroll
    for (int o = 0; o < C; o++) { s[o] = 0.f; q[o] = 0.f; }
    if (n < N_PTS) {
        float r[40];
        load20(r, &g_x2[n * C]);
#pragma unroll
        for (int c = 0; c < C; c++) r[c] = fmaxf(fmaf(r[c], ssc[c], sbi[c]), 0.f);
        load20(r + C, &feat[n * C]);
        float h[C];
#pragma unroll
        for (int o = 0; o < C; o++) {
            const float* w = &sW[o * 40];
            float a = sb[o];
#pragma unroll
            for (int c = 0; c < 40; c++) a = fmaf(w[c], r[c], a);
            h[o] = a; s[o] = a; q[o] = a * a;
        }
        store20(&g_h[n * C], h);
    }
    stats_reduce_store(s, q, blockIdx.x);
}

// output: out = Wr2 @ relu(bn3(h)) + br2
__global__ void __launch_bounds__(TPB) k_out(const float* __restrict__ Wr2,
                                             const float* __restrict__ br2,
                                             float* __restrict__ out) {
    __shared__ float sW[C * C], sb[C], ssc[C], sbi[C];
    for (int i = threadIdx.x; i < C * C; i += TPB) sW[i] = Wr2[i];
    if (threadIdx.x < C) {
        sb[threadIdx.x]  = br2[threadIdx.x];
        ssc[threadIdx.x] = g_scale[threadIdx.x];
        sbi[threadIdx.x] = g_bias[threadIdx.x];
    }
    __syncthreads();
    int n = blockIdx.x * TPB + threadIdx.x;
    if (n >= N_PTS) return;
    float r[C];
    load20(r, &g_h[n * C]);
#pragma unroll
    for (int c = 0; c < C; c++) r[c] = fmaxf(fmaf(r[c], ssc[c], sbi[c]), 0.f);
    float o_[C];
#pragma unroll
    for (int o = 0; o < C; o++) {
        const float* w = &sW[o * C];
        float a = sb[o];
#pragma unroll
        for (int c = 0; c < C; c++) a = fmaf(w[c], r[c], a);
        o_[o] = a;
    }
    store20(&out[n * C], o_);
}

// ---------------- launch ----------------------------------------------------
extern "C" void kernel_launch(void* const* d_in, const int* in_sizes, int n_in,
                              void* d_out, int out_size) {
    const float* pts  = (const float*)d_in[0];
    const float* feat = (const float*)d_in[1];
    const void*  idx  = d_in[2];
    const float* W1   = (const float*)d_in[3];
    const float* g1   = (const float*)d_in[4];
    const float* b1   = (const float*)d_in[5];
    const float* g2   = (const float*)d_in[6];
    const float* b2   = (const float*)d_in[7];
    const float* Wr1  = (const float*)d_in[8];
    const float* br1  = (const float*)d_in[9];
    const float* g3   = (const float*)d_in[10];
    const float* b3   = (const float*)d_in[11];
    const float* Wr2  = (const float*)d_in[12];
    const float* br2  = (const float*)d_in[13];
    float* out = (float*)d_out;

    k_detect<<<1, 32>>>(idx);
    k_prep<<<NBLK, TPB>>>(pts, feat, W1);

    // BN1 over (N, K)
    k_stats1<<<NBLK, TPB>>>(idx);
    k_reduce<<<40, 256>>>();
    k_final<<<1, 32>>>(g1, b1, 1.0f / (float)(N_PTS * KNN));

    // aggregation passes
    k_agg1<<<NBLK, TPB>>>(idx);
    k_agg2<<<NBLK, TPB>>>(idx);

    // BN2 over N
    k_reduce<<<40, 256>>>();
    k_final<<<1, 32>>>(g2, b2, 1.0f / (float)N_PTS);

    // refine linear 1 + BN3 stats
    k_refine1<<<NBLK, TPB>>>(feat, Wr1, br1);
    k_reduce<<<40, 256>>>();
    k_final<<<1, 32>>>(g3, b3, 1.0f / (float)N_PTS);

    // final linear
    k_out<<<NBLK, TPB>>>(Wr2, br2, out);
}

// round 5
// speedup vs baseline: 1.1005x; 1.1005x over previous
#include <cuda_runtime.h>
#include <cstdint>

#define N_PTS 1000000
#define KNN   9
#define C     20
#define CIN3  23
#define TPB   256
#define PPB   128                              // points per block (pair kernels)
#define NBLK2 ((N_PTS + PPB - 1) / PPB)        // 7813
#define NBLKR ((N_PTS + TPB - 1) / TPB)        // 3907
#define EPSV  1e-5f

// ---------------- scratch (device globals; allocation-free per contract) ----
__device__ __align__(16) float g_G0[N_PTS * C];   // W1f*feat + W1p*pts (per point)
__device__ __align__(16) float g_v [N_PTS * C];   // first weighted aggregation
__device__ __align__(16) float g_x2[N_PTS * C];   // second weighted aggregation
__device__ __align__(16) float g_h [N_PTS * C];   // pre-BN3 linear output
__device__ float g_wgt[N_PTS * KNN];              // attention weights w[n,k]
__device__ float g_part_t[40 * NBLK2];            // per-slot-major partials
__device__ float g_scale[C];                      // folded BN scale (per stage)
__device__ float g_bias[C];                       // folded BN bias
__device__ int   g_idx64;                         // 1 if index buffer is int64

// ---------------- helpers ---------------------------------------------------
__device__ __forceinline__ void load20(float* r, const float* p) {
    const float4* q = (const float4*)p;
#pragma unroll
    for (int i = 0; i < 5; i++) {
        float4 t = q[i];
        r[4*i] = t.x; r[4*i+1] = t.y; r[4*i+2] = t.z; r[4*i+3] = t.w;
    }
}
__device__ __forceinline__ void store20(float* p, const float* r) {
    float4* q = (float4*)p;
#pragma unroll
    for (int i = 0; i < 5; i++) {
        float4 t;
        t.x = r[4*i]; t.y = r[4*i+1]; t.z = r[4*i+2]; t.w = r[4*i+3];
        q[i] = t;
    }
}
__device__ __forceinline__ int fetch_idx(const void* p, int i, int is64) {
    return is64 ? (int)((const long long*)p)[i] : ((const int*)p)[i];
}
// row split: h=0 -> channels [0,12), h=1 -> channels [12,20). 16B-aligned both.
__device__ __forceinline__ void loadHalf(float* r, const float* row, int h) {
    const float4* q = (const float4*)(row + 12 * h);
    float4 a = q[0], b = q[1];
    r[0]=a.x; r[1]=a.y; r[2]=a.z; r[3]=a.w;
    r[4]=b.x; r[5]=b.y; r[6]=b.z; r[7]=b.w;
    if (h == 0) { float4 c = q[2]; r[8]=c.x; r[9]=c.y; r[10]=c.z; r[11]=c.w; }
}
__device__ __forceinline__ void storeHalf(float* row, const float* r, int h) {
    float4* q = (float4*)(row + 12 * h);
    float4 a, b;
    a.x=r[0]; a.y=r[1]; a.z=r[2]; a.w=r[3];
    b.x=r[4]; b.y=r[5]; b.z=r[6]; b.w=r[7];
    q[0] = a; q[1] = b;
    if (h == 0) { float4 c; c.x=r[8]; c.y=r[9]; c.z=r[10]; c.w=r[11]; q[2] = c; }
}

// pair-kernel block stats reduction: thread holds 12 (h=0) / 8 (h=1) channel
// partials for channels 12h+i ; writes 40 slot partials (sum 0..19, sumsq 20..39)
__device__ __forceinline__ void pair_stats_store(float* s, float* q, int h, int blk) {
#pragma unroll
    for (int i = 0; i < 12; i++) {
#pragma unroll
        for (int off = 16; off >= 2; off >>= 1) {   // parity-preserving reduce
            s[i] += __shfl_down_sync(0xffffffffu, s[i], off);
            q[i] += __shfl_down_sync(0xffffffffu, q[i], off);
        }
    }
    __shared__ float sh[8][40];
    int warp = threadIdx.x >> 5, lane = threadIdx.x & 31;
    if (lane == 0) {           // h=0 sums: channels 0..11
#pragma unroll
        for (int i = 0; i < 12; i++) { sh[warp][i] = s[i]; sh[warp][20+i] = q[i]; }
    }
    if (lane == 1) {           // h=1 sums: channels 12..19
#pragma unroll
        for (int i = 0; i < 8; i++) { sh[warp][12+i] = s[i]; sh[warp][32+i] = q[i]; }
    }
    __syncthreads();
    if (threadIdx.x < 40) {
        float a = 0.f;
#pragma unroll
        for (int w = 0; w < 8; w++) a += sh[w][threadIdx.x];
        g_part_t[threadIdx.x * NBLK2 + blk] = a;
    }
}

// per-point-kernel stats reduction (thread holds all 20 channels)
__device__ __forceinline__ void stats_reduce_store(float* s, float* q, int blk) {
#pragma unroll
    for (int o = 0; o < C; o++) {
#pragma unroll
        for (int off = 16; off > 0; off >>= 1) {
            s[o] += __shfl_down_sync(0xffffffffu, s[o], off);
            q[o] += __shfl_down_sync(0xffffffffu, q[o], off);
        }
    }
    __shared__ float sh[8][40];
    int warp = threadIdx.x >> 5, lane = threadIdx.x & 31;
    if (lane == 0) {
#pragma unroll
        for (int o = 0; o < C; o++) { sh[warp][o] = s[o]; sh[warp][20+o] = q[o]; }
    }
    __syncthreads();
    if (threadIdx.x < 40) {
        float a = 0.f;
#pragma unroll
        for (int w = 0; w < 8; w++) a += sh[w][threadIdx.x];
        g_part_t[threadIdx.x * NBLK2 + blk] = a;
    }
}

// ---------------- kernels ---------------------------------------------------

__global__ void k_detect(const void* idx) {
    if (threadIdx.x == 0) {
        const int* p = (const int*)idx;
        int odd_zero = 1;
        for (int i = 0; i < 64; i++)
            if (p[2 * i + 1] != 0) odd_zero = 0;
        g_idx64 = odd_zero;
    }
}

// per-point precompute: G0 = W1[:, :20]*feat + W1[:,20:]*pts
__global__ void __launch_bounds__(TPB) k_prep(const float* __restrict__ pts,
                                              const float* __restrict__ feat,
                                              const float* __restrict__ W1) {
    __shared__ float sW[C * CIN3];
    for (int i = threadIdx.x; i < C * CIN3; i += TPB) sW[i] = W1[i];
    __syncthreads();
    int n = blockIdx.x * TPB + threadIdx.x;
    if (n >= N_PTS) return;
    float f[C];
    load20(f, &feat[n * C]);
    float p0 = pts[n*3], p1 = pts[n*3+1], p2 = pts[n*3+2];
    float G[C];
#pragma unroll
    for (int o = 0; o < C; o++) {
        const float* w = &sW[o * CIN3];
        float acc = fmaf(w[22], p2, fmaf(w[21], p1, w[20] * p0));
#pragma unroll
        for (int c = 0; c < C; c++) acc = fmaf(w[c], f[c], acc);
        G[o] = acc;
    }
    store20(&g_G0[n * C], G);
}

// BN1 statistics over 9M of (G0[idx] - Wp*pts[n]) per channel. Pair layout.
__global__ void __launch_bounds__(TPB) k_stats1(const void* __restrict__ idxp,
                                                const float* __restrict__ pts,
                                                const float* __restrict__ W1) {
    __shared__ float sWp[60];   // sWp[d*20+o] = W1[o*23+20+d]
    int tid = threadIdx.x;
    if (tid < 60) sWp[tid] = W1[(tid % 20) * CIN3 + 20 + tid / 20];
    __syncthreads();
    int h  = tid & 1;
    int p  = blockIdx.x * PPB + (tid >> 1);
    bool valid = p < N_PTS;
    int pc = valid ? p : N_PTS - 1;
    int is64 = g_idx64;

    float px = pts[pc*3], py = pts[pc*3+1], pz = pts[pc*3+2];
    float pp[12];
#pragma unroll
    for (int i = 0; i < 12; i++) {
        int cg = 12*h + i; int c = cg < C ? cg : C - 1;
        pp[i] = fmaf(sWp[40+c], pz, fmaf(sWp[20+c], py, sWp[c] * px));
    }
    int jj[KNN];
#pragma unroll
    for (int k = 0; k < KNN; k++) jj[k] = fetch_idx(idxp, pc * KNN + k, is64);

    float s[12], q[12];
#pragma unroll
    for (int i = 0; i < 12; i++) { s[i] = 0.f; q[i] = 0.f; }
#pragma unroll
    for (int k = 0; k < KNN; k++) {
        float x[12];
        loadHalf(x, &g_G0[jj[k] * C], h);
#pragma unroll
        for (int i = 0; i < 8; i++) {
            float d = x[i] - pp[i];
            s[i] += d; q[i] = fmaf(d, d, q[i]);
        }
        if (h == 0) {
#pragma unroll
            for (int i = 8; i < 12; i++) {
                float d = x[i] - pp[i];
                s[i] += d; q[i] = fmaf(d, d, q[i]);
            }
        }
    }
    if (!valid) {
#pragma unroll
        for (int i = 0; i < 12; i++) { s[i] = 0.f; q[i] = 0.f; }
    }
    pair_stats_store(s, q, h, blockIdx.x);
}

// reduce g_part_t slices + fold BN -> scale/bias. grid = 20 (one block/channel)
__global__ void __launch_bounds__(256) k_reduce_final(const float* __restrict__ g,
                                                      const float* __restrict__ b,
                                                      float inv_count, int nblk) {
    int o = blockIdx.x;
    const float* p0 = g_part_t + o * NBLK2;
    const float* p1 = g_part_t + (20 + o) * NBLK2;
    float a0 = 0.f, a1 = 0.f;
    for (int i = threadIdx.x; i < nblk; i += 256) { a0 += p0[i]; a1 += p1[i]; }
    __shared__ float s0[256], s1[256];
    s0[threadIdx.x] = a0; s1[threadIdx.x] = a1;
    __syncthreads();
    for (int st = 128; st > 0; st >>= 1) {
        if (threadIdx.x < st) {
            s0[threadIdx.x] += s0[threadIdx.x + st];
            s1[threadIdx.x] += s1[threadIdx.x + st];
        }
        __syncthreads();
    }
    if (threadIdx.x == 0) {
        float mean = s0[0] * inv_count;
        float var  = fmaf(-mean, mean, s1[0] * inv_count);
        float x = var + EPSV;
        float r = rsqrtf(x);
        r = r * (1.5f - 0.5f * x * r * r);   // Newton refine
        float sc = g[o] * r;
        g_scale[o] = sc;
        g_bias[o]  = b[o] - mean * sc;
    }
}

// first aggregation (pair layout): x_k = s*G0[idx] + (t - s*Wp*pts[n]);
// w_k = x_k . x_0 ; v = sum_k x_k * w_k ; store w_k
__global__ void __launch_bounds__(TPB) k_agg1(const void* __restrict__ idxp,
                                              const float* __restrict__ pts,
                                              const float* __restrict__ W1) {
    __shared__ float sWp[60], ssc[C], sbi[C];
    int tid = threadIdx.x;
    if (tid < 60) sWp[tid] = W1[(tid % 20) * CIN3 + 20 + tid / 20];
    if (tid < C) { ssc[tid] = g_scale[tid]; sbi[tid] = g_bias[tid]; }
    __syncthreads();
    int h  = tid & 1;
    int p  = blockIdx.x * PPB + (tid >> 1);
    bool valid = p < N_PTS;
    int pc = valid ? p : N_PTS - 1;
    int is64 = g_idx64;

    float px = pts[pc*3], py = pts[pc*3+1], pz = pts[pc*3+2];
    float sc[12], base[12];
#pragma unroll
    for (int i = 0; i < 12; i++) {
        int cg = 12*h + i; int c = cg < C ? cg : C - 1;
        float pp = fmaf(sWp[40+c], pz, fmaf(sWp[20+c], py, sWp[c] * px));
        sc[i]   = ssc[c];
        base[i] = fmaf(-ssc[c], pp, sbi[c]);
    }
    int jj[KNN];
#pragma unroll
    for (int k = 0; k < KNN; k++) jj[k] = fetch_idx(idxp, pc * KNN + k, is64);

    // neighbor 0
    float x0[12];
    loadHalf(x0, &g_G0[jj[0] * C], h);
    float wp = 0.f;
#pragma unroll
    for (int i = 0; i < 8; i++) { x0[i] = fmaf(sc[i], x0[i], base[i]); wp = fmaf(x0[i], x0[i], wp); }
    if (h == 0) {
#pragma unroll
        for (int i = 8; i < 12; i++) { x0[i] = fmaf(sc[i], x0[i], base[i]); wp = fmaf(x0[i], x0[i], wp); }
    }
    float w0 = wp + __shfl_xor_sync(0xffffffffu, wp, 1);
    float v[12];
#pragma unroll
    for (int i = 0; i < 12; i++) v[i] = x0[i] * w0;
    if (valid && h == 0) g_wgt[p * KNN] = w0;

#pragma unroll
    for (int k = 1; k < KNN; k++) {
        float xk[12];
        loadHalf(xk, &g_G0[jj[k] * C], h);
        float dp = 0.f;
#pragma unroll
        for (int i = 0; i < 8; i++) { xk[i] = fmaf(sc[i], xk[i], base[i]); dp = fmaf(xk[i], x0[i], dp); }
        if (h == 0) {
#pragma unroll
            for (int i = 8; i < 12; i++) { xk[i] = fmaf(sc[i], xk[i], base[i]); dp = fmaf(xk[i], x0[i], dp); }
        }
        float wk = dp + __shfl_xor_sync(0xffffffffu, dp, 1);
#pragma unroll
        for (int i = 0; i < 8; i++) v[i] = fmaf(xk[i], wk, v[i]);
        if (h == 0) {
#pragma unroll
            for (int i = 8; i < 12; i++) v[i] = fmaf(xk[i], wk, v[i]);
        }
        if (valid && h == 0) g_wgt[p * KNN + k] = wk;
    }
    if (valid) storeHalf(&g_v[p * C], v, h);
}

// second aggregation (pair layout): x2 = sum_k v[idx] * w ; fused BN2 stats
__global__ void __launch_bounds__(TPB) k_agg2(const void* __restrict__ idxp) {
    int tid = threadIdx.x;
    int h  = tid & 1;
    int p  = blockIdx.x * PPB + (tid >> 1);
    bool valid = p < N_PTS;
    int pc = valid ? p : N_PTS - 1;
    int is64 = g_idx64;

    int jj[KNN];
    float wk[KNN];
#pragma unroll
    for (int k = 0; k < KNN; k++) {
        jj[k] = fetch_idx(idxp, pc * KNN + k, is64);
        wk[k] = g_wgt[pc * KNN + k];
    }
    float acc[12];
#pragma unroll
    for (int i = 0; i < 12; i++) acc[i] = 0.f;
#pragma unroll
    for (int k = 0; k < KNN; k++) {
        float x[12];
        loadHalf(x, &g_v[jj[k] * C], h);
#pragma unroll
        for (int i = 0; i < 8; i++) acc[i] = fmaf(x[i], wk[k], acc[i]);
        if (h == 0) {
#pragma unroll
            for (int i = 8; i < 12; i++) acc[i] = fmaf(x[i], wk[k], acc[i]);
        }
    }
    if (valid) storeHalf(&g_x2[p * C], acc, h);
    float s[12], q[12];
#pragma unroll
    for (int i = 0; i < 12; i++) {
        s[i] = valid ? acc[i] : 0.f;
        q[i] = valid ? acc[i] * acc[i] : 0.f;
    }
    pair_stats_store(s, q, h, blockIdx.x);
}

// refine stage 1: r = relu(bn2(x2)); h = Wr1 @ [r, feat] + br1; fused BN3 stats
__global__ void __launch_bounds__(TPB) k_refine1(const float* __restrict__ feat,
                                                 const float* __restrict__ Wr1,
                                                 const float* __restrict__ br1) {
    __shared__ float sW[C * 40], sb[C], ssc[C], sbi[C];
    for (int i = threadIdx.x; i < C * 40; i += TPB) sW[i] = Wr1[i];
    if (threadIdx.x < C) {
        sb[threadIdx.x]  = br1[threadIdx.x];
        ssc[threadIdx.x] = g_scale[threadIdx.x];
        sbi[threadIdx.x] = g_bias[threadIdx.x];
    }
    __syncthreads();
    int n = blockIdx.x * TPB + threadIdx.x;
    float s[C], q[C];
#pragma unroll
    for (int o = 0; o < C; o++) { s[o] = 0.f; q[o] = 0.f; }
    if (n < N_PTS) {
        float r[40];
        load20(r, &g_x2[n * C]);
#pragma unroll
        for (int c = 0; c < C; c++) r[c] = fmaxf(fmaf(r[c], ssc[c], sbi[c]), 0.f);
        load20(r + C, &feat[n * C]);
        float hh[C];
#pragma unroll
        for (int o = 0; o < C; o++) {
            const float* w = &sW[o * 40];
            float a = sb[o];
#pragma unroll
            for (int c = 0; c < 40; c++) a = fmaf(w[c], r[c], a);
            hh[o] = a; s[o] = a; q[o] = a * a;
        }
        store20(&g_h[n * C], hh);
    }
    stats_reduce_store(s, q, blockIdx.x);
}

// output: out = Wr2 @ relu(bn3(h)) + br2
__global__ void __launch_bounds__(TPB) k_out(const float* __restrict__ Wr2,
                                             const float* __restrict__ br2,
                                             float* __restrict__ out) {
    __shared__ float sW[C * C], sb[C], ssc[C], sbi[C];
    for (int i = threadIdx.x; i < C * C; i += TPB) sW[i] = Wr2[i];
    if (threadIdx.x < C) {
        sb[threadIdx.x]  = br2[threadIdx.x];
        ssc[threadIdx.x] = g_scale[threadIdx.x];
        sbi[threadIdx.x] = g_bias[threadIdx.x];
    }
    __syncthreads();
    int n = blockIdx.x * TPB + threadIdx.x;
    if (n >= N_PTS) return;
    float r[C];
    load20(r, &g_h[n * C]);
#pragma unroll
    for (int c = 0; c < C; c++) r[c] = fmaxf(fmaf(r[c], ssc[c], sbi[c]), 0.f);
    float o_[C];
#pragma unroll
    for (int o = 0; o < C; o++) {
        const float* w = &sW[o * C];
        float a = sb[o];
#pragma unroll
        for (int c = 0; c < C; c++) a = fmaf(w[c], r[c], a);
        o_[o] = a;
    }
    store20(&out[n * C], o_);
}

// ---------------- launch ----------------------------------------------------
extern "C" void kernel_launch(void* const* d_in, const int* in_sizes, int n_in,
                              void* d_out, int out_size) {
    const float* pts  = (const float*)d_in[0];
    const float* feat = (const float*)d_in[1];
    const void*  idx  = d_in[2];
    const float* W1   = (const float*)d_in[3];
    const float* g1   = (const float*)d_in[4];
    const float* b1   = (const float*)d_in[5];
    const float* g2   = (const float*)d_in[6];
    const float* b2   = (const float*)d_in[7];
    const float* Wr1  = (const float*)d_in[8];
    const float* br1  = (const float*)d_in[9];
    const float* g3   = (const float*)d_in[10];
    const float* b3   = (const float*)d_in[11];
    const float* Wr2  = (const float*)d_in[12];
    const float* br2  = (const float*)d_in[13];
    float* out = (float*)d_out;

    k_detect<<<1, 32>>>(idx);
    k_prep<<<NBLKR, TPB>>>(pts, feat, W1);

    // BN1 over (N, K)
    k_stats1<<<NBLK2, TPB>>>(idx, pts, W1);
    k_reduce_final<<<20, 256>>>(g1, b1, 1.0f / (float)(N_PTS * KNN), NBLK2);

    // aggregation passes
    k_agg1<<<NBLK2, TPB>>>(idx, pts, W1);
    k_agg2<<<NBLK2, TPB>>>(idx);

    // BN2 over N
    k_reduce_final<<<20, 256>>>(g2, b2, 1.0f / (float)N_PTS, NBLK2);

    // refine linear 1 + BN3 stats
    k_refine1<<<NBLKR, TPB>>>(feat, Wr1, br1);
    k_reduce_final<<<20, 256>>>(g3, b3, 1.0f / (float)N_PTS, NBLKR);

    // final linear
    k_out<<<NBLKR, TPB>>>(Wr2, br2, out);
}